// round 3
// baseline (speedup 1.0000x reference)
#include <cuda_runtime.h>
#include <cstdint>

#define VOCAB 50257
#define DIM 1024
#define BLANK_TOKEN_ID 100
#define B 4
#define S 4096

// One CTA per output row. 256 threads x float4 = 1024 floats = one row.
__global__ __launch_bounds__(256, 8)
void blank_embedding_kernel(const int* __restrict__ x,
                            const float* __restrict__ emb,
                            float* __restrict__ out)
{
    const int row = blockIdx.x;          // 0 .. B*S-1
    const int s   = row & (S - 1);       // position within sequence (S power of 2)
    const int tid = threadIdx.x;

    // Base gather: emb[x[row]]  (guard keeps us trap-free if dtype guess is off)
    int t0 = __ldg(&x[row]);
    if ((unsigned)t0 >= VOCAB) t0 = 0;
    const float4* e0 = reinterpret_cast<const float4*>(emb + (size_t)t0 * DIM);
    float4 acc = e0[tid];

    // Up to 3 conditional preblank contributions (block-uniform branches).
    // contribution from s-k iff x[s-k] != BLANK and x[s-k+1] == BLANK
#pragma unroll
    for (int k = 1; k <= 3; ++k) {
        if (s - k >= 0) {
            int tk        = __ldg(&x[row - k]);
            const int tk1 = __ldg(&x[row - k + 1]);
            if (tk != BLANK_TOKEN_ID && tk1 == BLANK_TOKEN_ID) {
                if ((unsigned)tk >= VOCAB) tk = 0;
                const float4* ek = reinterpret_cast<const float4*>(emb + (size_t)tk * DIM);
                const float4 v = ek[tid];
                acc.x += v.x; acc.y += v.y; acc.z += v.z; acc.w += v.w;
            }
        }
    }

    reinterpret_cast<float4*>(out + (size_t)row * DIM)[tid] = acc;
}

extern "C" void kernel_launch(void* const* d_in, const int* in_sizes, int n_in,
                              void* d_out, int out_size)
{
    const int* x     = (const int*)d_in[0];     // [B, S] int32 (JAX x64 disabled)
    const float* emb = (const float*)d_in[1];   // [VOCAB, DIM] f32
    float* out       = (float*)d_out;           // [B, S, DIM] f32

    blank_embedding_kernel<<<B * S, 256>>>(x, emb, out);
}

// round 4
// speedup vs baseline: 1.3509x; 1.3509x over previous
#include <cuda_runtime.h>
#include <cstdint>

#define VOCAB 50257
#define DIM 1024
#define BLANK_TOKEN_ID 100
#define B 4
#define S 4096
#define ROWS_PER_CTA 4

// 4 rows per CTA, 256 threads. Thread t owns float4 column t of each row.
// All 4 base gathers are issued before any dependent use -> MLP_eff ~ 4.
__global__ __launch_bounds__(256, 8)
void blank_embedding_kernel(const int* __restrict__ x,
                            const float* __restrict__ emb,
                            float* __restrict__ out)
{
    const int tid  = threadIdx.x;
    const int base = blockIdx.x * ROWS_PER_CTA;

    const float4* emb4 = reinterpret_cast<const float4*>(emb);
    float4* out4       = reinterpret_cast<float4*>(out);

    // Phase 1: read tokens, issue all 4 independent gathers.
    int rowv[ROWS_PER_CTA];
    float4 acc[ROWS_PER_CTA];
#pragma unroll
    for (int j = 0; j < ROWS_PER_CTA; ++j) {
        const int row = base + j;
        rowv[j] = row;
        int t0 = __ldg(&x[row]);
        if ((unsigned)t0 >= VOCAB) t0 = 0;
        acc[j] = __ldg(&emb4[(size_t)t0 * (DIM / 4) + tid]);
    }

    // Phase 2: rare preblank contributions (block-uniform branches).
    // contribution at s from s-k iff x[s-k] != BLANK and x[s-k+1] == BLANK
#pragma unroll
    for (int j = 0; j < ROWS_PER_CTA; ++j) {
        const int row = rowv[j];
        const int s   = row & (S - 1);
#pragma unroll
        for (int k = 1; k <= 3; ++k) {
            if (s - k >= 0) {
                int tk        = __ldg(&x[row - k]);
                const int tk1 = __ldg(&x[row - k + 1]);
                if (tk != BLANK_TOKEN_ID && tk1 == BLANK_TOKEN_ID) {
                    if ((unsigned)tk >= VOCAB) tk = 0;
                    const float4 v = __ldg(&emb4[(size_t)tk * (DIM / 4) + tid]);
                    acc[j].x += v.x; acc[j].y += v.y;
                    acc[j].z += v.z; acc[j].w += v.w;
                }
            }
        }
    }

    // Phase 3: streaming stores — output is never re-read, keep it out of L2.
#pragma unroll
    for (int j = 0; j < ROWS_PER_CTA; ++j) {
        __stcs(&out4[(size_t)rowv[j] * (DIM / 4) + tid], acc[j]);
    }
}

extern "C" void kernel_launch(void* const* d_in, const int* in_sizes, int n_in,
                              void* d_out, int out_size)
{
    const int* x     = (const int*)d_in[0];     // [B, S] int32
    const float* emb = (const float*)d_in[1];   // [VOCAB, DIM] f32
    float* out       = (float*)d_out;           // [B, S, DIM] f32

    blank_embedding_kernel<<<(B * S) / ROWS_PER_CTA, 256>>>(x, emb, out);
}